// round 7
// baseline (speedup 1.0000x reference)
#include <cuda_runtime.h>
#include <cuda_bf16.h>
#include <cstdint>

// ===================== problem constants =====================
#define BATCH 8192
#define DIM   2048
#define TILE  128
#define KC    128                   // fp8 K-elements per chunk = 128 bytes/row
#define NCHUNK (DIM / KC)           // 16
#define STAGES 3
#define TILE_SMEM 16384             // 128 rows * 128 bytes
#define STAGE_BYTES (2 * TILE_SMEM) // A tile + B tile
#define SMEM_TOTAL (STAGES * STAGE_BYTES)   // 98304 -> 2 CTAs/SM
#define NTILES (BATCH / TILE)       // 64
#define NBLOCKS (NTILES * (NTILES + 1) / 2) // 2080
#define FP8_SCALE 32.0f             // quantization scale; sim' = 1024 * sim
#define INV_SCALE2 (1.0f / 1024.0f)

// ===================== device scratch =====================
__device__ uint8_t g_x8[(size_t)BATCH * DIM];   // 16 MB normalized, scaled e4m3 rows
__device__ float g_pos[BATCH];
__device__ float g_oth[BATCH];

// ===================== asm helpers (base sm_100 compatible) =====================
__device__ __forceinline__ uint32_t smem_to_u32(const void* smem_ptr) {
    uint32_t addr;
    asm("{ .reg .u64 tmp; cvta.to.shared.u64 tmp, %1; cvt.u32.u64 %0, tmp; }"
        : "=r"(addr) : "l"(smem_ptr));
    return addr;
}

#define CP_ASYNC_16(saddr, gptr) \
    asm volatile("cp.async.cg.shared.global [%0], [%1], 16;" :: "r"(saddr), "l"(gptr))
#define CP_COMMIT() asm volatile("cp.async.commit_group;" ::: "memory")
#define CP_WAIT(n)  asm volatile("cp.async.wait_group %0;" :: "n"(n) : "memory")

#define LDMATRIX_X4(r0, r1, r2, r3, addr) \
    asm volatile("ldmatrix.sync.aligned.m8n8.x4.shared.b16 {%0,%1,%2,%3}, [%4];" \
        : "=r"(r0), "=r"(r1), "=r"(r2), "=r"(r3) : "r"(addr))

// fp8 e4m3 MMA, K=32 per instruction (2x FLOP/instr vs bf16 k16)
#define MMA_FP8(c0, c1, c2, c3, a0, a1, a2, a3, b0, b1) \
    asm volatile("mma.sync.aligned.m16n8k32.row.col.f32.e4m3.e4m3.f32 " \
        "{%0,%1,%2,%3}, {%4,%5,%6,%7}, {%8,%9}, {%0,%1,%2,%3};" \
        : "+f"(c0), "+f"(c1), "+f"(c2), "+f"(c3) \
        : "r"(a0), "r"(a1), "r"(a2), "r"(a3), "r"(b0), "r"(b1))

// pack 4 floats -> 4 e4m3 bytes (byte k = v[k])
__device__ __forceinline__ uint32_t pack_e4m3x4(float v0, float v1, float v2, float v3) {
    unsigned short p01, p23;
    asm("cvt.rn.satfinite.e4m3x2.f32 %0, %1, %2;" : "=h"(p01) : "f"(v1), "f"(v0));
    asm("cvt.rn.satfinite.e4m3x2.f32 %0, %1, %2;" : "=h"(p23) : "f"(v3), "f"(v2));
    return (uint32_t)p01 | ((uint32_t)p23 << 16);
}

// ===================== kernel 1: normalize rows -> scaled e4m3, zero accumulators ============
__global__ __launch_bounds__(256) void snn_norm_kernel(const float* __restrict__ x) {
    int row = blockIdx.x;
    int tid = threadIdx.x;
    const float4* x4 = reinterpret_cast<const float4*>(x + (size_t)row * DIM);
    float4 a = x4[tid];
    float4 b = x4[tid + 256];
    float ss = a.x*a.x + a.y*a.y + a.z*a.z + a.w*a.w
             + b.x*b.x + b.y*b.y + b.z*b.z + b.w*b.w;
    #pragma unroll
    for (int o = 16; o > 0; o >>= 1) ss += __shfl_xor_sync(0xffffffffu, ss, o);
    __shared__ float wsum[8];
    __shared__ float s_tot;
    if ((tid & 31) == 0) wsum[tid >> 5] = ss;
    __syncthreads();
    if (tid == 0) {
        float t = 0.f;
        #pragma unroll
        for (int i = 0; i < 8; i++) t += wsum[i];
        s_tot = t;
        g_pos[row] = 0.f;
        g_oth[row] = 0.f;
    }
    __syncthreads();
    float rn = rsqrtf(s_tot) * FP8_SCALE;
    uint32_t* o4 = reinterpret_cast<uint32_t*>(g_x8 + (size_t)row * DIM);
    o4[tid]       = pack_e4m3x4(a.x * rn, a.y * rn, a.z * rn, a.w * rn);
    o4[tid + 256] = pack_e4m3x4(b.x * rn, b.y * rn, b.z * rn, b.w * rn);
}

// ===================== kernel 2: triangular Gram + exp + masked sums =====================
// Loads one K-chunk (A rows, B rows; 128 rows x 128 bytes each) into XOR-swizzled smem.
__device__ __forceinline__ void load_chunk(uint32_t smem_u, uint32_t stage_off,
                                           const uint4* __restrict__ x16,
                                           int rowA0, int rowB0, int kvec, int tid) {
    #pragma unroll
    for (int u = 0; u < 8; u++) {
        int v = tid + u * 256;          // 0..2047
        int which = v >> 10;            // 0 = A tile, 1 = B tile
        int idx = v & 1023;
        int r  = idx >> 3;              // row within tile
        int cc = idx & 7;               // 16B column within 128B chunk
        int grow = (which ? rowB0 : rowA0) + r;
        const uint4* gp = x16 + (size_t)grow * (DIM / 16) + kvec + cc;
        uint32_t boff = stage_off + (uint32_t)which * TILE_SMEM
                      + (uint32_t)(r * 128) + (uint32_t)((cc * 16) ^ ((r & 7) << 4));
        CP_ASYNC_16(smem_u + boff, gp);
    }
}

__global__ __launch_bounds__(256) void snn_gram_kernel(const int* __restrict__ y) {
    extern __shared__ char smem[];
    uint32_t smem_u = smem_to_u32(smem);
    __shared__ int s_yi[128], s_yj[128];

    int tid = threadIdx.x;
    int wid = tid >> 5;
    int lane = tid & 31;

    // map linear block id -> upper-triangle tile (bi <= bj)
    int t = blockIdx.x;
    int bi = 0;
    #pragma unroll 1
    for (;;) {
        int rowlen = NTILES - bi;
        if (t < rowlen) break;
        t -= rowlen;
        bi++;
    }
    int bj = bi + t;
    int rowA0 = bi * TILE;
    int rowB0 = bj * TILE;
    bool diag = (bi == bj);

    // labels are int32 (JAX x64 disabled downcasts int64 -> int32)
    if (tid < 128) s_yi[tid] = y[rowA0 + tid];
    else           s_yj[tid - 128] = y[rowB0 + tid - 128];

    const uint4* x16 = reinterpret_cast<const uint4*>(g_x8);

    // warp layout: 4 (M) x 2 (N). warp tile 32 x 64.
    int wm = wid >> 1;           // 0..3 -> rows wm*32
    int wn = wid & 1;            // 0..1 -> cols wn*64
    int rquad = lane >> 2;       // 0..7
    int cpair = lane & 3;        // 0..3

    // per-lane ldmatrix base offsets (stage-independent)
    uint32_t a_off[2], a_xor[2];
    #pragma unroll
    for (int mf = 0; mf < 2; mf++) {
        int arow = wm * 32 + mf * 16 + (lane & 15);
        a_off[mf] = (uint32_t)(arow * 128);
        a_xor[mf] = (uint32_t)((arow & 7) << 4);
    }
    uint32_t b_off[4], b_xor[4];
    #pragma unroll
    for (int nf2 = 0; nf2 < 4; nf2++) {
        int brow = wn * 64 + nf2 * 16 + (lane & 15);
        b_off[nf2] = (uint32_t)(TILE_SMEM + brow * 128);
        b_xor[nf2] = (uint32_t)((brow & 7) << 4);
    }
    uint32_t kbl = (uint32_t)((lane >> 4) * 16);  // 16B half select within 32B k-step

    float acc[2][8][4];
    #pragma unroll
    for (int mf = 0; mf < 2; mf++)
        #pragma unroll
        for (int nf = 0; nf < 8; nf++)
            #pragma unroll
            for (int r = 0; r < 4; r++) acc[mf][nf][r] = 0.f;

    // prologue: stages 0..STAGES-2
    #pragma unroll
    for (int s = 0; s < STAGES - 1; s++) {
        load_chunk(smem_u, (uint32_t)s * STAGE_BYTES, x16, rowA0, rowB0, s * 8, tid);
        CP_COMMIT();
    }

    for (int c = 0; c < NCHUNK; c++) {
        CP_WAIT(STAGES - 2);
        __syncthreads();

        int nc = c + STAGES - 1;
        if (nc < NCHUNK) {
            load_chunk(smem_u, (uint32_t)(nc % STAGES) * STAGE_BYTES, x16,
                       rowA0, rowB0, nc * 8, tid);
        }
        CP_COMMIT();

        uint32_t sbase = smem_u + (uint32_t)(c % STAGES) * STAGE_BYTES;
        #pragma unroll
        for (int step = 0; step < 4; step++) {      // 4 x k32 = 128 fp8 per chunk
            uint32_t kb = (uint32_t)(step * 32) + kbl;
            uint32_t af[2][4];
            #pragma unroll
            for (int mf = 0; mf < 2; mf++) {
                uint32_t addr = sbase + a_off[mf] + (kb ^ a_xor[mf]);
                LDMATRIX_X4(af[mf][0], af[mf][1], af[mf][2], af[mf][3], addr);
            }
            uint32_t bf[8][2];
            #pragma unroll
            for (int nf2 = 0; nf2 < 4; nf2++) {
                uint32_t addr = sbase + b_off[nf2] + (kb ^ b_xor[nf2]);
                uint32_t r0, r1, r2, r3;
                LDMATRIX_X4(r0, r1, r2, r3, addr);
                // x4: r0=n0-7/k0-15, r1=n8-15/k0-15, r2=n0-7/k16-31, r3=n8-15/k16-31
                bf[2*nf2][0]   = r0; bf[2*nf2][1]   = r2;
                bf[2*nf2+1][0] = r1; bf[2*nf2+1][1] = r3;
            }
            #pragma unroll
            for (int nf = 0; nf < 8; nf++)
                #pragma unroll
                for (int mf = 0; mf < 2; mf++)
                    MMA_FP8(acc[mf][nf][0], acc[mf][nf][1], acc[mf][nf][2], acc[mf][nf][3],
                            af[mf][0], af[mf][1], af[mf][2], af[mf][3],
                            bf[nf][0], bf[nf][1]);
        }
    }
    CP_WAIT(0);

    // ===================== epilogue =====================
    // element (mf, nf, reg): row_local = wm*32+mf*16+(reg>>1)*8+rquad
    //                        col_local = wn*64+nf*8+cpair*2+(reg&1)
    int rl[2][2], yiv[2][2];
    #pragma unroll
    for (int mf = 0; mf < 2; mf++)
        #pragma unroll
        for (int h = 0; h < 2; h++) {
            rl[mf][h] = wm * 32 + mf * 16 + h * 8 + rquad;
            yiv[mf][h] = s_yi[rl[mf][h]];
        }
    int cl[8][2], yjv[8][2];
    #pragma unroll
    for (int nf = 0; nf < 8; nf++)
        #pragma unroll
        for (int rb = 0; rb < 2; rb++) {
            cl[nf][rb] = wn * 64 + nf * 8 + cpair * 2 + rb;
            yjv[nf][rb] = s_yj[cl[nf][rb]];
        }

    float rp[2][2] = {{0,0},{0,0}}, ro[2][2] = {{0,0},{0,0}};
    float cp_[8][2], co[8][2];
    #pragma unroll
    for (int nf = 0; nf < 8; nf++) { cp_[nf][0]=cp_[nf][1]=0.f; co[nf][0]=co[nf][1]=0.f; }

    #pragma unroll
    for (int mf = 0; mf < 2; mf++)
        #pragma unroll
        for (int nf = 0; nf < 8; nf++)
            #pragma unroll
            for (int r = 0; r < 4; r++) {
                int h = r >> 1, rb = r & 1;
                // acc = 1024 * sim; e = exp(-sim)/TEMP
                float e = 2.0f * __expf(-acc[mf][nf][r] * INV_SCALE2);
                bool excl = diag && (rl[mf][h] == cl[nf][rb]);
                bool same = (yiv[mf][h] == yjv[nf][rb]);
                if (!excl) {
                    ro[mf][h] += e;
                    if (same) rp[mf][h] += e;
                }
                co[nf][rb] += e;               // col sums used only when !diag
                if (same) cp_[nf][rb] += e;
            }

    // row sums: reduce across cpair lanes (xor 1, 2), lane cpair==0 commits
    #pragma unroll
    for (int mf = 0; mf < 2; mf++)
        #pragma unroll
        for (int h = 0; h < 2; h++) {
            float vo = ro[mf][h], vp = rp[mf][h];
            vo += __shfl_xor_sync(0xffffffffu, vo, 1);
            vo += __shfl_xor_sync(0xffffffffu, vo, 2);
            vp += __shfl_xor_sync(0xffffffffu, vp, 1);
            vp += __shfl_xor_sync(0xffffffffu, vp, 2);
            if (cpair == 0) {
                int gi = rowA0 + rl[mf][h];
                atomicAdd(&g_oth[gi], vo);
                atomicAdd(&g_pos[gi], vp);
            }
        }

    // col sums (off-diagonal blocks only; symmetric contribution to j rows):
    // reduce across rquad lanes (xor 4, 8, 16), lanes rquad==0 commit
    if (!diag) {
        #pragma unroll
        for (int nf = 0; nf < 8; nf++)
            #pragma unroll
            for (int rb = 0; rb < 2; rb++) {
                float vo = co[nf][rb], vp = cp_[nf][rb];
                vo += __shfl_xor_sync(0xffffffffu, vo, 4);
                vo += __shfl_xor_sync(0xffffffffu, vo, 8);
                vo += __shfl_xor_sync(0xffffffffu, vo, 16);
                vp += __shfl_xor_sync(0xffffffffu, vp, 4);
                vp += __shfl_xor_sync(0xffffffffu, vp, 8);
                vp += __shfl_xor_sync(0xffffffffu, vp, 16);
                if (rquad == 0) {
                    int gj = rowB0 + cl[nf][rb];
                    atomicAdd(&g_oth[gj], vo);
                    atomicAdd(&g_pos[gj], vp);
                }
            }
    }
}

// ===================== kernel 3: final loss reduction =====================
__global__ __launch_bounds__(256) void snn_finalize_kernel(float* __restrict__ out) {
    int tid = threadIdx.x;
    __shared__ double sred[256];
    double acc = 0.0;
    for (int i = tid; i < BATCH; i += 256) {
        float p = g_pos[i] + 1e-10f;
        float o = g_oth[i] + 1e-10f;
        acc += (double)logf(p / o);
    }
    sred[tid] = acc;
    __syncthreads();
    for (int s = 128; s > 0; s >>= 1) {
        if (tid < s) sred[tid] += sred[tid + s];
        __syncthreads();
    }
    if (tid == 0) out[0] = (float)(-sred[0] / (double)BATCH);
}

// ===================== launch =====================
extern "C" void kernel_launch(void* const* d_in, const int* in_sizes, int n_in,
                              void* d_out, int out_size) {
    const float* x = (const float*)d_in[0];
    const int* y = (const int*)d_in[1];
    float* out = (float*)d_out;

    cudaFuncSetAttribute(snn_gram_kernel,
                         cudaFuncAttributeMaxDynamicSharedMemorySize, SMEM_TOTAL);

    snn_norm_kernel<<<BATCH, 256>>>(x);
    snn_gram_kernel<<<NBLOCKS, 256, SMEM_TOTAL>>>(y);
    snn_finalize_kernel<<<1, 256>>>(out);
}

// round 8
// speedup vs baseline: 1.6526x; 1.6526x over previous
#include <cuda_runtime.h>
#include <cuda_bf16.h>
#include <cstdint>

// ===================== problem constants =====================
#define BATCH 8192
#define DIM   2048
#define TILE  128
#define KC    128                   // int8 K-elements per chunk = 128 bytes/row
#define NCHUNK (DIM / KC)           // 16
#define STAGES 3
#define TILE_SMEM 16384             // 128 rows * 128 bytes
#define STAGE_BYTES (2 * TILE_SMEM) // A tile + B tile
#define SMEM_TOTAL (STAGES * STAGE_BYTES)   // 98304 -> 2 CTAs/SM
#define NTILES (BATCH / TILE)       // 64
#define NBLOCKS (NTILES * (NTILES + 1) / 2) // 2080
#define QSCALE 768.0f               // int8 quantization scale
#define INV_S2 (1.0f / (QSCALE * QSCALE))

// ===================== device scratch =====================
__device__ int8_t g_x8[(size_t)BATCH * DIM];   // 16 MB normalized, scaled int8 rows
__device__ float g_pos[BATCH];
__device__ float g_oth[BATCH];
__device__ int g_ctr;                           // zero-initialized; reset by last CTA

// ===================== asm helpers (base sm_100 compatible) =====================
__device__ __forceinline__ uint32_t smem_to_u32(const void* smem_ptr) {
    uint32_t addr;
    asm("{ .reg .u64 tmp; cvta.to.shared.u64 tmp, %1; cvt.u32.u64 %0, tmp; }"
        : "=r"(addr) : "l"(smem_ptr));
    return addr;
}

#define CP_ASYNC_16(saddr, gptr) \
    asm volatile("cp.async.cg.shared.global [%0], [%1], 16;" :: "r"(saddr), "l"(gptr))
#define CP_COMMIT() asm volatile("cp.async.commit_group;" ::: "memory")
#define CP_WAIT(n)  asm volatile("cp.async.wait_group %0;" :: "n"(n) : "memory")

#define LDMATRIX_X4(r0, r1, r2, r3, addr) \
    asm volatile("ldmatrix.sync.aligned.m8n8.x4.shared.b16 {%0,%1,%2,%3}, [%4];" \
        : "=r"(r0), "=r"(r1), "=r"(r2), "=r"(r3) : "r"(addr))

// int8 IMMA, K=32 per instruction, exact s32 accumulate
#define MMA_S8(c0, c1, c2, c3, a0, a1, a2, a3, b0, b1) \
    asm volatile("mma.sync.aligned.m16n8k32.row.col.s32.s8.s8.s32 " \
        "{%0,%1,%2,%3}, {%4,%5,%6,%7}, {%8,%9}, {%0,%1,%2,%3};" \
        : "+r"(c0), "+r"(c1), "+r"(c2), "+r"(c3) \
        : "r"(a0), "r"(a1), "r"(a2), "r"(a3), "r"(b0), "r"(b1))

__device__ __forceinline__ int q8(float v) {
    int t = __float2int_rn(v);
    return max(-127, min(127, t));
}

// ===================== kernel 1: normalize rows -> scaled int8, zero accumulators ============
__global__ __launch_bounds__(256) void snn_norm_kernel(const float* __restrict__ x) {
    int row = blockIdx.x;
    int tid = threadIdx.x;
    const float4* x4 = reinterpret_cast<const float4*>(x + (size_t)row * DIM);
    float4 a = x4[tid];
    float4 b = x4[tid + 256];
    float ss = a.x*a.x + a.y*a.y + a.z*a.z + a.w*a.w
             + b.x*b.x + b.y*b.y + b.z*b.z + b.w*b.w;
    #pragma unroll
    for (int o = 16; o > 0; o >>= 1) ss += __shfl_xor_sync(0xffffffffu, ss, o);
    __shared__ float wsum[8];
    __shared__ float s_tot;
    if ((tid & 31) == 0) wsum[tid >> 5] = ss;
    __syncthreads();
    if (tid == 0) {
        float t = 0.f;
        #pragma unroll
        for (int i = 0; i < 8; i++) t += wsum[i];
        s_tot = t;
        g_pos[row] = 0.f;
        g_oth[row] = 0.f;
    }
    __syncthreads();
    float rn = rsqrtf(s_tot) * QSCALE;
    uint32_t* o4 = reinterpret_cast<uint32_t*>(g_x8 + (size_t)row * DIM);
    int a0 = q8(a.x*rn), a1 = q8(a.y*rn), a2 = q8(a.z*rn), a3 = q8(a.w*rn);
    int b0 = q8(b.x*rn), b1 = q8(b.y*rn), b2 = q8(b.z*rn), b3 = q8(b.w*rn);
    o4[tid]       = (uint32_t)(a0 & 255) | ((uint32_t)(a1 & 255) << 8)
                  | ((uint32_t)(a2 & 255) << 16) | ((uint32_t)(a3 & 255) << 24);
    o4[tid + 256] = (uint32_t)(b0 & 255) | ((uint32_t)(b1 & 255) << 8)
                  | ((uint32_t)(b2 & 255) << 16) | ((uint32_t)(b3 & 255) << 24);
}

// ===================== kernel 2: triangular Gram + exp + masked sums + fused finalize ========
__device__ __forceinline__ void load_chunk(uint32_t smem_u, uint32_t stage_off,
                                           const uint4* __restrict__ x16,
                                           int rowA0, int rowB0, int kvec, int tid) {
    #pragma unroll
    for (int u = 0; u < 8; u++) {
        int v = tid + u * 256;          // 0..2047
        int which = v >> 10;            // 0 = A tile, 1 = B tile
        int idx = v & 1023;
        int r  = idx >> 3;              // row within tile
        int cc = idx & 7;               // 16B column within 128B chunk
        int grow = (which ? rowB0 : rowA0) + r;
        const uint4* gp = x16 + (size_t)grow * (DIM / 16) + kvec + cc;
        uint32_t boff = stage_off + (uint32_t)which * TILE_SMEM
                      + (uint32_t)(r * 128) + (uint32_t)((cc * 16) ^ ((r & 7) << 4));
        CP_ASYNC_16(smem_u + boff, gp);
    }
}

__global__ __launch_bounds__(256) void snn_gram_kernel(const int* __restrict__ y,
                                                       float* __restrict__ out) {
    extern __shared__ char smem[];
    uint32_t smem_u = smem_to_u32(smem);
    __shared__ int s_yi[128], s_yj[128];

    int tid = threadIdx.x;
    int wid = tid >> 5;
    int lane = tid & 31;

    // map linear block id -> upper-triangle tile (bi <= bj)
    int t = blockIdx.x;
    int bi = 0;
    #pragma unroll 1
    for (;;) {
        int rowlen = NTILES - bi;
        if (t < rowlen) break;
        t -= rowlen;
        bi++;
    }
    int bj = bi + t;
    int rowA0 = bi * TILE;
    int rowB0 = bj * TILE;
    bool diag = (bi == bj);

    // labels are int32 (JAX x64 disabled downcasts int64 -> int32)
    if (tid < 128) s_yi[tid] = y[rowA0 + tid];
    else           s_yj[tid - 128] = y[rowB0 + tid - 128];

    const uint4* x16 = reinterpret_cast<const uint4*>(g_x8);

    // warp layout: 4 (M) x 2 (N). warp tile 32 x 64.
    int wm = wid >> 1;           // 0..3 -> rows wm*32
    int wn = wid & 1;            // 0..1 -> cols wn*64
    int rquad = lane >> 2;       // 0..7
    int cpair = lane & 3;        // 0..3

    uint32_t a_off[2], a_xor[2];
    #pragma unroll
    for (int mf = 0; mf < 2; mf++) {
        int arow = wm * 32 + mf * 16 + (lane & 15);
        a_off[mf] = (uint32_t)(arow * 128);
        a_xor[mf] = (uint32_t)((arow & 7) << 4);
    }
    uint32_t b_off[4], b_xor[4];
    #pragma unroll
    for (int nf2 = 0; nf2 < 4; nf2++) {
        int brow = wn * 64 + nf2 * 16 + (lane & 15);
        b_off[nf2] = (uint32_t)(TILE_SMEM + brow * 128);
        b_xor[nf2] = (uint32_t)((brow & 7) << 4);
    }
    uint32_t kbl = (uint32_t)((lane >> 4) * 16);  // 16B half select within 32B k-step

    int acc[2][8][4];
    #pragma unroll
    for (int mf = 0; mf < 2; mf++)
        #pragma unroll
        for (int nf = 0; nf < 8; nf++)
            #pragma unroll
            for (int r = 0; r < 4; r++) acc[mf][nf][r] = 0;

    #pragma unroll
    for (int s = 0; s < STAGES - 1; s++) {
        load_chunk(smem_u, (uint32_t)s * STAGE_BYTES, x16, rowA0, rowB0, s * 8, tid);
        CP_COMMIT();
    }

    for (int c = 0; c < NCHUNK; c++) {
        CP_WAIT(STAGES - 2);
        __syncthreads();

        int nc = c + STAGES - 1;
        if (nc < NCHUNK) {
            load_chunk(smem_u, (uint32_t)(nc % STAGES) * STAGE_BYTES, x16,
                       rowA0, rowB0, nc * 8, tid);
        }
        CP_COMMIT();

        uint32_t sbase = smem_u + (uint32_t)(c % STAGES) * STAGE_BYTES;
        #pragma unroll
        for (int step = 0; step < 4; step++) {      // 4 x k32 = 128 int8 per chunk
            uint32_t kb = (uint32_t)(step * 32) + kbl;
            uint32_t af[2][4];
            #pragma unroll
            for (int mf = 0; mf < 2; mf++) {
                uint32_t addr = sbase + a_off[mf] + (kb ^ a_xor[mf]);
                LDMATRIX_X4(af[mf][0], af[mf][1], af[mf][2], af[mf][3], addr);
            }
            uint32_t bf[8][2];
            #pragma unroll
            for (int nf2 = 0; nf2 < 4; nf2++) {
                uint32_t addr = sbase + b_off[nf2] + (kb ^ b_xor[nf2]);
                uint32_t r0, r1, r2, r3;
                LDMATRIX_X4(r0, r1, r2, r3, addr);
                // x4: r0=n0-7/k0-15, r1=n8-15/k0-15, r2=n0-7/k16-31, r3=n8-15/k16-31
                bf[2*nf2][0]   = r0; bf[2*nf2][1]   = r2;
                bf[2*nf2+1][0] = r1; bf[2*nf2+1][1] = r3;
            }
            #pragma unroll
            for (int nf = 0; nf < 8; nf++)
                #pragma unroll
                for (int mf = 0; mf < 2; mf++)
                    MMA_S8(acc[mf][nf][0], acc[mf][nf][1], acc[mf][nf][2], acc[mf][nf][3],
                           af[mf][0], af[mf][1], af[mf][2], af[mf][3],
                           bf[nf][0], bf[nf][1]);
        }
    }
    CP_WAIT(0);

    // ===================== epilogue =====================
    int rl[2][2], yiv[2][2];
    #pragma unroll
    for (int mf = 0; mf < 2; mf++)
        #pragma unroll
        for (int h = 0; h < 2; h++) {
            rl[mf][h] = wm * 32 + mf * 16 + h * 8 + rquad;
            yiv[mf][h] = s_yi[rl[mf][h]];
        }
    int cl[8][2], yjv[8][2];
    #pragma unroll
    for (int nf = 0; nf < 8; nf++)
        #pragma unroll
        for (int rb = 0; rb < 2; rb++) {
            cl[nf][rb] = wn * 64 + nf * 8 + cpair * 2 + rb;
            yjv[nf][rb] = s_yj[cl[nf][rb]];
        }

    float rp[2][2] = {{0,0},{0,0}}, ro[2][2] = {{0,0},{0,0}};
    float cp_[8][2], co[8][2];
    #pragma unroll
    for (int nf = 0; nf < 8; nf++) { cp_[nf][0]=cp_[nf][1]=0.f; co[nf][0]=co[nf][1]=0.f; }

    #pragma unroll
    for (int mf = 0; mf < 2; mf++)
        #pragma unroll
        for (int nf = 0; nf < 8; nf++)
            #pragma unroll
            for (int r = 0; r < 4; r++) {
                int h = r >> 1, rb = r & 1;
                float sim = (float)acc[mf][nf][r] * INV_S2;
                float e = 2.0f * __expf(-sim);   // exp(-sim)/TEMP
                bool excl = diag && (rl[mf][h] == cl[nf][rb]);
                bool same = (yiv[mf][h] == yjv[nf][rb]);
                if (!excl) {
                    ro[mf][h] += e;
                    if (same) rp[mf][h] += e;
                }
                co[nf][rb] += e;
                if (same) cp_[nf][rb] += e;
            }

    #pragma unroll
    for (int mf = 0; mf < 2; mf++)
        #pragma unroll
        for (int h = 0; h < 2; h++) {
            float vo = ro[mf][h], vp = rp[mf][h];
            vo += __shfl_xor_sync(0xffffffffu, vo, 1);
            vo += __shfl_xor_sync(0xffffffffu, vo, 2);
            vp += __shfl_xor_sync(0xffffffffu, vp, 1);
            vp += __shfl_xor_sync(0xffffffffu, vp, 2);
            if (cpair == 0) {
                int gi = rowA0 + rl[mf][h];
                atomicAdd(&g_oth[gi], vo);
                atomicAdd(&g_pos[gi], vp);
            }
        }

    if (!diag) {
        #pragma unroll
        for (int nf = 0; nf < 8; nf++)
            #pragma unroll
            for (int rb = 0; rb < 2; rb++) {
                float vo = co[nf][rb], vp = cp_[nf][rb];
                vo += __shfl_xor_sync(0xffffffffu, vo, 4);
                vo += __shfl_xor_sync(0xffffffffu, vo, 8);
                vo += __shfl_xor_sync(0xffffffffu, vo, 16);
                vp += __shfl_xor_sync(0xffffffffu, vp, 4);
                vp += __shfl_xor_sync(0xffffffffu, vp, 8);
                vp += __shfl_xor_sync(0xffffffffu, vp, 16);
                if (rquad == 0) {
                    int gj = rowB0 + cl[nf][rb];
                    atomicAdd(&g_oth[gj], vo);
                    atomicAdd(&g_pos[gj], vp);
                }
            }
    }

    // ===================== fused finalize (last CTA) =====================
    __threadfence();
    __shared__ int s_last;
    __syncthreads();            // all atomics of this CTA issued before the fence above
    if (tid == 0) s_last = (atomicAdd(&g_ctr, 1) == NBLOCKS - 1);
    __syncthreads();
    if (s_last) {
        __threadfence();        // acquire: all other CTAs' fenced writes now visible
        __shared__ double sred[256];
        double accd = 0.0;
        for (int i = tid; i < BATCH; i += 256) {
            float p = g_pos[i] + 1e-10f;
            float o = g_oth[i] + 1e-10f;
            accd += (double)logf(p / o);
        }
        sred[tid] = accd;
        __syncthreads();
        for (int s = 128; s > 0; s >>= 1) {
            if (tid < s) sred[tid] += sred[tid + s];
            __syncthreads();
        }
        if (tid == 0) {
            out[0] = (float)(-sred[0] / (double)BATCH);
            g_ctr = 0;          // reset for next (graph-replayed) call
        }
    }
}

// ===================== launch =====================
extern "C" void kernel_launch(void* const* d_in, const int* in_sizes, int n_in,
                              void* d_out, int out_size) {
    const float* x = (const float*)d_in[0];
    const int* y = (const int*)d_in[1];
    float* out = (float*)d_out;

    cudaFuncSetAttribute(snn_gram_kernel,
                         cudaFuncAttributeMaxDynamicSharedMemorySize, SMEM_TOTAL);

    snn_norm_kernel<<<BATCH, 256>>>(x);
    snn_gram_kernel<<<NBLOCKS, 256, SMEM_TOTAL>>>(y, out);
}